// round 5
// baseline (speedup 1.0000x reference)
#include <cuda_runtime.h>
#include <cuda_bf16.h>

// GraphConvDistanceLayer: out[i] = sum_{e: rows[e]==i} Param_W[params[e]] * x[cols[e]]
//                                 + Param_b[b_params[i]]
//
// Inputs (metadata order):
//   d_in[0] = x        float32 [N]      N = 262144
//   d_in[1] = Param_W  float32 [1280]
//   d_in[2] = Param_b  float32 [16]
//   d_in[3] = w_rows   int32   [E]      E = 16777216
//   d_in[4] = w_cols   int32   [E]
//   d_in[5] = w_params int32   [E]
//   d_in[6] = b_params int32   [N]
// Output: float32 [N]

#define GCD_NPARAMS 1280

// ---------------------------------------------------------------------------
// Kernel 1: initialize out with the bias gather (d_out arrives poisoned).
// ---------------------------------------------------------------------------
__global__ __launch_bounds__(256)
void gcd_bias_init(float* __restrict__ out,
                   const float* __restrict__ Pb,
                   const int* __restrict__ bp,
                   int n) {
    int i = blockIdx.x * blockDim.x + threadIdx.x;
    if (i < n) {
        out[i] = __ldg(&Pb[__ldg(&bp[i])]);
    }
}

// ---------------------------------------------------------------------------
// Kernel 2: edge scatter. 4 edges per thread via int4 index loads (coalesced
// LDG.128 on the three index streams — the only DRAM-heavy traffic, 201 MB).
// Param_W (5 KB) is staged in shared memory: random LDS ~4 cyc/warp-instr vs
// ~64 cyc of L1tex wavefronts for a fully divergent LDG. x (1 MB) gathers
// from L2 via __ldg. Accumulation via atomicAdd -> RED (no return).
// ---------------------------------------------------------------------------
__global__ __launch_bounds__(256)
void gcd_edge_scatter(const float* __restrict__ x,
                      const float* __restrict__ Pw,
                      const int4* __restrict__ rows,
                      const int4* __restrict__ cols,
                      const int4* __restrict__ params,
                      float* __restrict__ out,
                      int e4) {
    __shared__ float sPw[GCD_NPARAMS];
    for (int i = threadIdx.x; i < GCD_NPARAMS; i += blockDim.x)
        sPw[i] = Pw[i];
    __syncthreads();

    int i = blockIdx.x * blockDim.x + threadIdx.x;
    if (i >= e4) return;

    // Coalesced 16B loads of 4 edges' indices.
    int4 r = rows[i];
    int4 c = cols[i];
    int4 p = params[i];

    // Issue all 4 x-gathers before consuming (MLP=4 on the L2-latency path).
    float xa = __ldg(&x[c.x]);
    float xb = __ldg(&x[c.y]);
    float xc = __ldg(&x[c.z]);
    float xd = __ldg(&x[c.w]);

    float v0 = sPw[p.x] * xa;
    float v1 = sPw[p.y] * xb;
    float v2 = sPw[p.z] * xc;
    float v3 = sPw[p.w] * xd;

    atomicAdd(&out[r.x], v0);
    atomicAdd(&out[r.y], v1);
    atomicAdd(&out[r.z], v2);
    atomicAdd(&out[r.w], v3);
}

// Scalar tail (E % 4 != 0) — defensive; E = 2^24 here so normally unused.
__global__ __launch_bounds__(128)
void gcd_edge_tail(const float* __restrict__ x,
                   const float* __restrict__ Pw,
                   const int* __restrict__ rows,
                   const int* __restrict__ cols,
                   const int* __restrict__ params,
                   float* __restrict__ out,
                   int start, int E) {
    int e = start + blockIdx.x * blockDim.x + threadIdx.x;
    if (e < E) {
        float v = __ldg(&Pw[__ldg(&params[e])]) * __ldg(&x[__ldg(&cols[e])]);
        atomicAdd(&out[__ldg(&rows[e])], v);
    }
}

extern "C" void kernel_launch(void* const* d_in, const int* in_sizes, int n_in,
                              void* d_out, int out_size) {
    const float* x   = (const float*)d_in[0];
    const float* Pw  = (const float*)d_in[1];
    const float* Pb  = (const float*)d_in[2];
    const int* rows  = (const int*)d_in[3];
    const int* cols  = (const int*)d_in[4];
    const int* prm   = (const int*)d_in[5];
    const int* bp    = (const int*)d_in[6];
    float* out       = (float*)d_out;

    const int N = out_size;
    const int E = in_sizes[3];

    // 1) out = Param_b[b_params]  (also clears the 0xAA poison)
    gcd_bias_init<<<(N + 255) / 256, 256>>>(out, Pb, bp, N);

    // 2) scatter-accumulate the edges
    const int e4 = E >> 2;
    if (e4 > 0) {
        gcd_edge_scatter<<<(e4 + 255) / 256, 256>>>(
            x, Pw,
            (const int4*)rows, (const int4*)cols, (const int4*)prm,
            out, e4);
    }
    const int tail_start = e4 << 2;
    const int tail = E - tail_start;
    if (tail > 0) {
        gcd_edge_tail<<<(tail + 127) / 128, 128>>>(
            x, Pw, rows, cols, prm, out, tail_start, E);
    }
}